// round 6
// baseline (speedup 1.0000x reference)
#include <cuda_runtime.h>
#include <math_constants.h>
#include <cstdint>

#define QLEN  65536
#define EDIM  256
#define NH    8
#define DHEAD 32
#define KNBR  16

// Scratch (allocation-free rule: __device__ globals)
__device__ float g_q[(size_t)QLEN * EDIM];
__device__ float g_k[(size_t)QLEN * EDIM];
__device__ float g_v[(size_t)QLEN * EDIM];
__device__ float g_attn[(size_t)QLEN * EDIM];
__device__ uint32_t g_wt[4 * 256 * 256];   // pre-converted tf32 weights: q,k,v,out

// ---------------------------------------------------------------------------
// PTX helpers
// ---------------------------------------------------------------------------
__device__ __forceinline__ uint32_t f2tf32(float x) {
    uint32_t r;
    asm("cvt.rna.tf32.f32 %0, %1;" : "=r"(r) : "f"(x));
    return r;
}

__device__ __forceinline__ void mma_tf32(float c[4], const uint32_t a[4], const uint32_t b[2]) {
    asm volatile(
        "mma.sync.aligned.m16n8k8.row.col.f32.tf32.tf32.f32 "
        "{%0,%1,%2,%3}, {%4,%5,%6,%7}, {%8,%9}, {%0,%1,%2,%3};"
        : "+f"(c[0]), "+f"(c[1]), "+f"(c[2]), "+f"(c[3])
        : "r"(a[0]), "r"(a[1]), "r"(a[2]), "r"(a[3]), "r"(b[0]), "r"(b[1]));
}

__device__ __forceinline__ void cp_async16(void* dst, const void* src) {
    uint32_t d = (uint32_t)__cvta_generic_to_shared(dst);
    asm volatile("cp.async.cg.shared.global [%0], [%1], 16;" :: "r"(d), "l"(src));
}
__device__ __forceinline__ void cp_commit() { asm volatile("cp.async.commit_group;"); }
__device__ __forceinline__ void cp_wait0() { asm volatile("cp.async.wait_group 0;"); }
__device__ __forceinline__ void cp_wait1() { asm volatile("cp.async.wait_group 1;"); }

__device__ __forceinline__ void ldsm_x4(uint32_t r[4], const uint32_t* saddr) {
    uint32_t a = (uint32_t)__cvta_generic_to_shared(saddr);
    asm volatile("ldmatrix.sync.aligned.m8n8.x4.shared.b16 {%0,%1,%2,%3}, [%4];"
        : "=r"(r[0]), "=r"(r[1]), "=r"(r[2]), "=r"(r[3]) : "r"(a));
}

// ---------------------------------------------------------------------------
// Weight pre-convert: fp32 -> tf32 bits (256KB total, trivial kernel)
// layout: g_wt[0:64K)=Wq, [64K:128K)=Wk, [128K:192K)=Wv, [192K:256K)=Wout
// ---------------------------------------------------------------------------
__global__ void cvt_weights_kernel(const float* __restrict__ Wall,
                                   const float* __restrict__ Wout)
{
    int i = blockIdx.x * 256 + threadIdx.x;
    float v = (i < 3 * 65536) ? Wall[i] : Wout[i - 3 * 65536];
    g_wt[i] = f2tf32(v);
}

// ---------------------------------------------------------------------------
// TF32 GEMM v2: cp.async double-buffered, ldmatrix fragments.
// C[M,256] = (A[M,256] @ W[256,256]^T + bias) * scale
// Block 128x128, BK=32, 2 smem stages, 256 threads = 8 warps (4M x 2N),
// warp tile 32x64 = 2x8 m16n8k8.
// ---------------------------------------------------------------------------
#define SST 36            // padded row stride in words (ldmatrix conflict-free)
#define STAGE_WORDS 9216  // (128*36)*2 arrays per stage

__device__ __forceinline__ void gemm_prefetch(const float* __restrict__ A,
                                              const uint32_t* __restrict__ Wt,
                                              uint32_t* sA, uint32_t* sB,
                                              int mBase, int nBase, int kc,
                                              int prow, int kq)
{
#pragma unroll
    for (int p = 0; p < 4; p++) {
        int r = prow + p * 32;
        cp_async16(sA + r * SST + kq * 4, A  + (size_t)(mBase + r) * 256 + kc + kq * 4);
        cp_async16(sB + r * SST + kq * 4, Wt + (size_t)(nBase + r) * 256 + kc + kq * 4);
    }
}

__device__ __forceinline__ void gemm256_v2(const float* __restrict__ A,
                                           const uint32_t* __restrict__ Wt,
                                           const float* __restrict__ bias,
                                           float* __restrict__ C,
                                           float scale)
{
    extern __shared__ uint32_t sm[];   // 2 stages x (A 4608 + B 4608) words

    const int tid   = threadIdx.x;
    const int lane  = tid & 31;
    const int warp  = tid >> 5;
    const int g     = lane >> 2;
    const int t     = lane & 3;
    const int warpM = warp >> 1;
    const int warpN = warp & 1;
    const int mBase = blockIdx.y * 128;
    const int nBase = blockIdx.x * 128;
    const int kq    = tid & 7;
    const int prow  = tid >> 3;

    // ldmatrix per-lane address components (4 tiles: [m0..7|m8..15] x [k0|k0+4])
    const int lq = lane >> 3;            // tile id 0..3
    const int lr = lane & 7;             // row within tile
    const int aRow  = warpM * 32 + (lq & 1) * 8 + lr;
    const int bRowB = warpN * 64 + (lq & 1) * 8 + lr;
    const int colOf = (lq >> 1) * 4;

    float acc[2][8][4];
#pragma unroll
    for (int ma = 0; ma < 2; ma++)
#pragma unroll
        for (int na = 0; na < 8; na++)
#pragma unroll
            for (int i = 0; i < 4; i++) acc[ma][na][i] = 0.f;

    gemm_prefetch(A, Wt, sm, sm + 4608, mBase, nBase, 0, prow, kq);
    cp_commit();

    for (int it = 0; it < 8; ++it) {
        if (it < 7) {
            uint32_t* st = sm + ((it + 1) & 1) * STAGE_WORDS;
            gemm_prefetch(A, Wt, st, st + 4608, mBase, nBase, (it + 1) * 32, prow, kq);
            cp_commit();
            cp_wait1();
        } else {
            cp_wait0();
        }
        __syncthreads();

        uint32_t* sA = sm + (it & 1) * STAGE_WORDS;
        uint32_t* sB = sA + 4608;

#pragma unroll
        for (int ks = 0; ks < 4; ks++) {
            const int k0 = ks * 8;
            uint32_t a[2][4];
#pragma unroll
            for (int ma = 0; ma < 2; ma++) {
                ldsm_x4(a[ma], sA + (aRow + ma * 16) * SST + k0 + colOf);
#pragma unroll
                for (int i = 0; i < 4; i++)
                    a[ma][i] = f2tf32(__uint_as_float(a[ma][i]));
            }
            uint32_t b[8][2];
#pragma unroll
            for (int n2 = 0; n2 < 4; n2++) {
                uint32_t r4[4];
                ldsm_x4(r4, sB + (bRowB + n2 * 16) * SST + k0 + colOf);
                b[2 * n2][0] = r4[0]; b[2 * n2 + 1][0] = r4[1];
                b[2 * n2][1] = r4[2]; b[2 * n2 + 1][1] = r4[3];
            }
#pragma unroll
            for (int ma = 0; ma < 2; ma++)
#pragma unroll
                for (int na = 0; na < 8; na++)
                    mma_tf32(acc[ma][na], a[ma], b[na]);
        }
        __syncthreads();
    }

    // epilogue: bias + scale, float2 stores
#pragma unroll
    for (int ma = 0; ma < 2; ma++) {
        int row0 = mBase + warpM * 32 + ma * 16 + g;
#pragma unroll
        for (int na = 0; na < 8; na++) {
            int col = nBase + warpN * 64 + na * 8 + t * 2;
            float2 bb = *(const float2*)(bias + col);
            float2 o0, o1;
            o0.x = (acc[ma][na][0] + bb.x) * scale;
            o0.y = (acc[ma][na][1] + bb.y) * scale;
            o1.x = (acc[ma][na][2] + bb.x) * scale;
            o1.y = (acc[ma][na][3] + bb.y) * scale;
            *(float2*)(C + (size_t)row0 * 256 + col) = o0;
            *(float2*)(C + (size_t)(row0 + 8) * 256 + col) = o1;
        }
    }
}

__global__ __launch_bounds__(256, 2)
void qkv_proj_kernel(const float* __restrict__ q_in,
                     const float* __restrict__ k_in,
                     const float* __restrict__ v_in,
                     const float* __restrict__ ball)
{
    const float* A;
    const float* b;
    float* C;
    float scale;
    const uint32_t* Wt;
    if (blockIdx.z == 0) {
        A = q_in; Wt = g_wt;              b = ball;       C = g_q;
        scale = 0.17677669529663687f;     // 1/sqrt(32)
    } else if (blockIdx.z == 1) {
        A = k_in; Wt = g_wt + 65536;      b = ball + 256; C = g_k; scale = 1.f;
    } else {
        A = v_in; Wt = g_wt + 131072;     b = ball + 512; C = g_v; scale = 1.f;
    }
    gemm256_v2(A, Wt, b, C, scale);
}

__global__ __launch_bounds__(256, 2)
void outproj_kernel(const float* __restrict__ bout, float* __restrict__ out)
{
    gemm256_v2(g_attn, g_wt + 196608, bout, out, 1.f);
}

// ---------------------------------------------------------------------------
// Attention v2: 1 block (256 thr) per query. Low-shfl design:
//  logit stage: warp w handles neighbors j=2w,2w+1; lane covers 8 contiguous
//    floats (head h=lane>>2, slice s=lane&3) -> 2 shfls per neighbor.
//  softmax: through smem [16][9] (conflict-free column reads).
//  V stage: thread <-> output element (coalesced 128B row reads, 0 shfls).
// ---------------------------------------------------------------------------
__global__ __launch_bounds__(256)
void attn_kernel(const int* __restrict__ idx,
                 float* __restrict__ w_out,
                 int write_w)
{
    const int q    = blockIdx.x;
    const int tid  = threadIdx.x;
    const int lane = tid & 31;
    const int warp = tid >> 5;

    __shared__ int   sidx[KNBR];
    __shared__ float sq[EDIM];
    __shared__ float slog[KNBR][9];
    __shared__ float sexp[KNBR][9];
    __shared__ float sw[KNBR][9];

    if (tid < KNBR) sidx[tid] = idx[q * KNBR + tid];
    if (tid < 64) ((float4*)sq)[tid] = ((const float4*)(g_q + (size_t)q * EDIM))[tid];
    __syncthreads();

    // ---- logits ----
    const int h   = lane >> 2;        // head 0..7
    const int s   = lane & 3;         // quarter within head
    const int off = h * 32 + s * 8;   // lane*8: warp reads a full contiguous row
    float qr[8];
    *(float4*)&qr[0] = *(const float4*)(sq + off);
    *(float4*)&qr[4] = *(const float4*)(sq + off + 4);

#pragma unroll
    for (int b = 0; b < 2; b++) {
        int j   = warp * 2 + b;
        int kj  = sidx[j];
        int kjc = max(kj, 0);
        const float4* kr = (const float4*)(g_k + (size_t)kjc * EDIM + off);
        float4 k0 = kr[0], k1 = kr[1];
        float p;
        p = qr[0] * k0.x;
        p = fmaf(qr[1], k0.y, p);
        p = fmaf(qr[2], k0.z, p);
        p = fmaf(qr[3], k0.w, p);
        p = fmaf(qr[4], k1.x, p);
        p = fmaf(qr[5], k1.y, p);
        p = fmaf(qr[6], k1.z, p);
        p = fmaf(qr[7], k1.w, p);
        p += __shfl_xor_sync(0xffffffffu, p, 1);
        p += __shfl_xor_sync(0xffffffffu, p, 2);
        if (s == 0) slog[j][h] = (kj >= 0) ? p : -CUDART_INF_F;
    }
    __syncthreads();

    // ---- softmax (threads 0..127: thread <-> (j,h)) ----
    float m = -CUDART_INF_F, e = 0.f;
    int jj = 0, hh = 0;
    if (tid < 128) {
        jj = tid >> 3; hh = tid & 7;
#pragma unroll
        for (int x = 0; x < KNBR; x++) m = fmaxf(m, slog[x][hh]);
        if (m != -CUDART_INF_F) e = __expf(slog[jj][hh] - m);  // exp(-inf)=0
        sexp[jj][hh] = e;
    }
    __syncthreads();
    if (tid < 128) {
        float S = 0.f;
#pragma unroll
        for (int x = 0; x < KNBR; x++) S += sexp[x][hh];
        float w = (m != -CUDART_INF_F) ? e / S : 0.f;
        sw[jj][hh] = w;
    }
    __syncthreads();

    // ---- weighted V gather: thread <-> output element tid ----
    const int h2 = tid >> 5;
    float o = 0.f;
#pragma unroll
    for (int j = 0; j < KNBR; j++) {
        int kjc = max(sidx[j], 0);
        float wv = sw[j][h2];
        o = fmaf(wv, g_v[(size_t)kjc * EDIM + tid], o);
    }
    g_attn[(size_t)q * EDIM + tid] = o;

    if (write_w && tid < KNBR) {
        float acc = 0.f;
#pragma unroll
        for (int x = 0; x < NH; x++) acc += sw[tid][x];
        w_out[q * KNBR + tid] = acc * 0.125f;
    }
}

// ---------------------------------------------------------------------------
extern "C" void kernel_launch(void* const* d_in, const int* in_sizes, int n_in,
                              void* d_out, int out_size)
{
    const float* q_in = (const float*)d_in[0];
    const float* k_in = (const float*)d_in[1];
    const float* v_in = (const float*)d_in[2];
    const int*   idx  = (const int*)  d_in[3];
    const float* Wall = (const float*)d_in[4];
    const float* ball = (const float*)d_in[5];
    const float* Wout = (const float*)d_in[6];
    const float* bout = (const float*)d_in[7];
    float* out = (float*)d_out;

    const int SMEM = 2 * STAGE_WORDS * 4;   // 73728 B
    cudaFuncSetAttribute(qkv_proj_kernel, cudaFuncAttributeMaxDynamicSharedMemorySize, SMEM);
    cudaFuncSetAttribute(outproj_kernel,  cudaFuncAttributeMaxDynamicSharedMemorySize, SMEM);

    // 0) weights -> tf32 bits (256K elements)
    cvt_weights_kernel<<<1024, 256>>>(Wall, Wout);

    // 1) fused q/k/v projections
    dim3 gproj(2, 512, 3);
    qkv_proj_kernel<<<gproj, 256, SMEM>>>(q_in, k_in, v_in, ball);

    // 2) gather attention (+ averaged weights, second output)
    int write_w = (out_size >= QLEN * (EDIM + KNBR)) ? 1 : 0;
    attn_kernel<<<QLEN, 256>>>(idx, out + (size_t)QLEN * EDIM, write_w);

    // 3) output projection -> d_out[0 : Q*E]
    dim3 gout(2, 512, 1);
    outproj_kernel<<<gout, 256, SMEM>>>(bout, out);
}

// round 8
// speedup vs baseline: 1.1556x; 1.1556x over previous
#include <cuda_runtime.h>
#include <math_constants.h>
#include <cstdint>

#define QLEN  65536
#define EDIM  256
#define NH    8
#define DHEAD 32
#define KNBR  16

// Scratch (allocation-free rule: __device__ globals)
__device__ float g_q[(size_t)QLEN * EDIM];
__device__ float g_k[(size_t)QLEN * EDIM];
__device__ float g_v[(size_t)QLEN * EDIM];
__device__ float g_attn[(size_t)QLEN * EDIM];
__device__ uint32_t g_wt[4 * 256 * 256];   // pre-converted tf32 weights: q,k,v,out

// ---------------------------------------------------------------------------
// PTX helpers
// ---------------------------------------------------------------------------
__device__ __forceinline__ uint32_t f2tf32(float x) {
    uint32_t r;
    asm("cvt.rna.tf32.f32 %0, %1;" : "=r"(r) : "f"(x));
    return r;
}

__device__ __forceinline__ void mma_tf32(float c[4], const uint32_t a[4], const uint32_t b[2]) {
    asm volatile(
        "mma.sync.aligned.m16n8k8.row.col.f32.tf32.tf32.f32 "
        "{%0,%1,%2,%3}, {%4,%5,%6,%7}, {%8,%9}, {%0,%1,%2,%3};"
        : "+f"(c[0]), "+f"(c[1]), "+f"(c[2]), "+f"(c[3])
        : "r"(a[0]), "r"(a[1]), "r"(a[2]), "r"(a[3]), "r"(b[0]), "r"(b[1]));
}

__device__ __forceinline__ void cp_async16(void* dst, const void* src) {
    uint32_t d = (uint32_t)__cvta_generic_to_shared(dst);
    asm volatile("cp.async.cg.shared.global [%0], [%1], 16;" :: "r"(d), "l"(src));
}
__device__ __forceinline__ void cp_commit() { asm volatile("cp.async.commit_group;"); }
__device__ __forceinline__ void cp_wait0() { asm volatile("cp.async.wait_group 0;"); }
__device__ __forceinline__ void cp_wait1() { asm volatile("cp.async.wait_group 1;"); }

__device__ __forceinline__ void ldsm_x4(uint32_t r[4], const uint32_t* saddr) {
    uint32_t a = (uint32_t)__cvta_generic_to_shared(saddr);
    asm volatile("ldmatrix.sync.aligned.m8n8.x4.shared.b16 {%0,%1,%2,%3}, [%4];"
        : "=r"(r[0]), "=r"(r[1]), "=r"(r[2]), "=r"(r[3]) : "r"(a));
}

// ---------------------------------------------------------------------------
// Weight pre-convert: fp32 -> tf32 bits
// ---------------------------------------------------------------------------
__global__ void cvt_weights_kernel(const float* __restrict__ Wall,
                                   const float* __restrict__ Wout)
{
    int i = blockIdx.x * 256 + threadIdx.x;
    float v = (i < 3 * 65536) ? Wall[i] : Wout[i - 3 * 65536];
    g_wt[i] = f2tf32(v);
}

// ---------------------------------------------------------------------------
// TF32 GEMM: cp.async double-buffered, ldmatrix fragments.
// C[M,256] = (A[M,256] @ W[256,256]^T + bias) * scale
// ---------------------------------------------------------------------------
#define SST 36
#define STAGE_WORDS 9216

__device__ __forceinline__ void gemm_prefetch(const float* __restrict__ A,
                                              const uint32_t* __restrict__ Wt,
                                              uint32_t* sA, uint32_t* sB,
                                              int mBase, int nBase, int kc,
                                              int prow, int kq)
{
#pragma unroll
    for (int p = 0; p < 4; p++) {
        int r = prow + p * 32;
        cp_async16(sA + r * SST + kq * 4, A  + (size_t)(mBase + r) * 256 + kc + kq * 4);
        cp_async16(sB + r * SST + kq * 4, Wt + (size_t)(nBase + r) * 256 + kc + kq * 4);
    }
}

__device__ __forceinline__ void gemm256_v2(const float* __restrict__ A,
                                           const uint32_t* __restrict__ Wt,
                                           const float* __restrict__ bias,
                                           float* __restrict__ C,
                                           float scale)
{
    extern __shared__ uint32_t sm[];

    const int tid   = threadIdx.x;
    const int lane  = tid & 31;
    const int warp  = tid >> 5;
    const int g     = lane >> 2;
    const int t     = lane & 3;
    const int warpM = warp >> 1;
    const int warpN = warp & 1;
    const int mBase = blockIdx.y * 128;
    const int nBase = blockIdx.x * 128;
    const int kq    = tid & 7;
    const int prow  = tid >> 3;

    const int lq = lane >> 3;
    const int lr = lane & 7;
    const int aRow  = warpM * 32 + (lq & 1) * 8 + lr;
    const int bRowB = warpN * 64 + (lq & 1) * 8 + lr;
    const int colOf = (lq >> 1) * 4;

    float acc[2][8][4];
#pragma unroll
    for (int ma = 0; ma < 2; ma++)
#pragma unroll
        for (int na = 0; na < 8; na++)
#pragma unroll
            for (int i = 0; i < 4; i++) acc[ma][na][i] = 0.f;

    gemm_prefetch(A, Wt, sm, sm + 4608, mBase, nBase, 0, prow, kq);
    cp_commit();

    for (int it = 0; it < 8; ++it) {
        if (it < 7) {
            uint32_t* st = sm + ((it + 1) & 1) * STAGE_WORDS;
            gemm_prefetch(A, Wt, st, st + 4608, mBase, nBase, (it + 1) * 32, prow, kq);
            cp_commit();
            cp_wait1();
        } else {
            cp_wait0();
        }
        __syncthreads();

        uint32_t* sA = sm + (it & 1) * STAGE_WORDS;
        uint32_t* sB = sA + 4608;

#pragma unroll
        for (int ks = 0; ks < 4; ks++) {
            const int k0 = ks * 8;
            uint32_t a[2][4];
#pragma unroll
            for (int ma = 0; ma < 2; ma++) {
                ldsm_x4(a[ma], sA + (aRow + ma * 16) * SST + k0 + colOf);
#pragma unroll
                for (int i = 0; i < 4; i++)
                    a[ma][i] = f2tf32(__uint_as_float(a[ma][i]));
            }
            uint32_t b[8][2];
#pragma unroll
            for (int n2 = 0; n2 < 4; n2++) {
                uint32_t r4[4];
                ldsm_x4(r4, sB + (bRowB + n2 * 16) * SST + k0 + colOf);
                b[2 * n2][0] = r4[0]; b[2 * n2 + 1][0] = r4[1];
                b[2 * n2][1] = r4[2]; b[2 * n2 + 1][1] = r4[3];
            }
#pragma unroll
            for (int ma = 0; ma < 2; ma++)
#pragma unroll
                for (int na = 0; na < 8; na++)
                    mma_tf32(acc[ma][na], a[ma], b[na]);
        }
        __syncthreads();
    }

#pragma unroll
    for (int ma = 0; ma < 2; ma++) {
        int row0 = mBase + warpM * 32 + ma * 16 + g;
#pragma unroll
        for (int na = 0; na < 8; na++) {
            int col = nBase + warpN * 64 + na * 8 + t * 2;
            float2 bb = *(const float2*)(bias + col);
            float2 o0, o1;
            o0.x = (acc[ma][na][0] + bb.x) * scale;
            o0.y = (acc[ma][na][1] + bb.y) * scale;
            o1.x = (acc[ma][na][2] + bb.x) * scale;
            o1.y = (acc[ma][na][3] + bb.y) * scale;
            *(float2*)(C + (size_t)row0 * 256 + col) = o0;
            *(float2*)(C + (size_t)(row0 + 8) * 256 + col) = o1;
        }
    }
}

__global__ __launch_bounds__(256, 2)
void qkv_proj_kernel(const float* __restrict__ q_in,
                     const float* __restrict__ k_in,
                     const float* __restrict__ v_in,
                     const float* __restrict__ ball)
{
    const float* A;
    const float* b;
    float* C;
    float scale;
    const uint32_t* Wt;
    if (blockIdx.z == 0) {
        A = q_in; Wt = g_wt;              b = ball;       C = g_q;
        scale = 0.17677669529663687f;     // 1/sqrt(32)
    } else if (blockIdx.z == 1) {
        A = k_in; Wt = g_wt + 65536;      b = ball + 256; C = g_k; scale = 1.f;
    } else {
        A = v_in; Wt = g_wt + 131072;     b = ball + 512; C = g_v; scale = 1.f;
    }
    gemm256_v2(A, Wt, b, C, scale);
}

__global__ __launch_bounds__(256, 2)
void outproj_kernel(const float* __restrict__ bout, float* __restrict__ out)
{
    gemm256_v2(g_attn, g_wt + 196608, bout, out, 1.f);
}

// ---------------------------------------------------------------------------
// Attention v3: one WARP per query, 8 queries/block, zero barriers, zero smem.
//  lane covers 8 contiguous floats: head h = lane>>2, slice s = lane&3.
//  logits: 1 idx-shfl + 2 xor-shfls per neighbor (4-lane head reduction);
//  softmax fully in registers (dup x4 per head); V accum in 8 registers.
// ---------------------------------------------------------------------------
__global__ __launch_bounds__(256)
void attn_kernel(const int* __restrict__ idx,
                 float* __restrict__ w_out,
                 int write_w)
{
    const int lane = threadIdx.x & 31;
    const int warp = threadIdx.x >> 5;
    const int q    = blockIdx.x * 8 + warp;
    const int off  = lane * 8;            // = (lane>>2)*32 + (lane&3)*8

    int myIdx = (lane < KNBR) ? idx[q * KNBR + lane] : -1;

    const float4* qp = (const float4*)(g_q + (size_t)q * EDIM + off);
    float4 q0 = qp[0], q1 = qp[1];

    // ---- logits (per-lane: logit of head lane>>2) ----
    float logit[KNBR];
#pragma unroll
    for (int j = 0; j < KNBR; j++) {
        int kj  = __shfl_sync(0xffffffffu, myIdx, j);
        int kjc = max(kj, 0);
        const float4* kp = (const float4*)(g_k + (size_t)kjc * EDIM + off);
        float4 k0 = kp[0], k1 = kp[1];
        float p;
        p = q0.x * k0.x;
        p = fmaf(q0.y, k0.y, p);
        p = fmaf(q0.z, k0.z, p);
        p = fmaf(q0.w, k0.w, p);
        p = fmaf(q1.x, k1.x, p);
        p = fmaf(q1.y, k1.y, p);
        p = fmaf(q1.z, k1.z, p);
        p = fmaf(q1.w, k1.w, p);
        p += __shfl_xor_sync(0xffffffffu, p, 1);
        p += __shfl_xor_sync(0xffffffffu, p, 2);
        logit[j] = (kj >= 0) ? p : -CUDART_INF_F;
    }

    // ---- register softmax ----
    float m = logit[0];
#pragma unroll
    for (int j = 1; j < KNBR; j++) m = fmaxf(m, logit[j]);

    float w[KNBR];
    if (m == -CUDART_INF_F) {
#pragma unroll
        for (int j = 0; j < KNBR; j++) w[j] = 0.f;
    } else {
        float s = 0.f;
#pragma unroll
        for (int j = 0; j < KNBR; j++) {
            w[j] = __expf(logit[j] - m);   // exp(-inf)=0 kills invalid slots
            s += w[j];
        }
        float inv = 1.f / s;
#pragma unroll
        for (int j = 0; j < KNBR; j++) w[j] *= inv;
    }

    // ---- weighted V accumulation ----
    float o[8];
#pragma unroll
    for (int i = 0; i < 8; i++) o[i] = 0.f;
#pragma unroll
    for (int j = 0; j < KNBR; j++) {
        int kjc = max(__shfl_sync(0xffffffffu, myIdx, j), 0);
        const float4* vp = (const float4*)(g_v + (size_t)kjc * EDIM + off);
        float4 v0 = vp[0], v1 = vp[1];
        float wj = w[j];
        o[0] = fmaf(wj, v0.x, o[0]);
        o[1] = fmaf(wj, v0.y, o[1]);
        o[2] = fmaf(wj, v0.z, o[2]);
        o[3] = fmaf(wj, v0.w, o[3]);
        o[4] = fmaf(wj, v1.x, o[4]);
        o[5] = fmaf(wj, v1.y, o[5]);
        o[6] = fmaf(wj, v1.z, o[6]);
        o[7] = fmaf(wj, v1.w, o[7]);
    }
    float4* op = (float4*)(g_attn + (size_t)q * EDIM + off);
    op[0] = make_float4(o[0], o[1], o[2], o[3]);
    op[1] = make_float4(o[4], o[5], o[6], o[7]);

    // ---- averaged weights ----
    // xor 4,8,16 reduces across lane bits 2..4 = the 8 heads, each counted
    // exactly once (the x4 duplication lives in bits 0..1 and never enters
    // the sum). So divide by NH=8 only.
    if (write_w) {
        float ws = 0.f;
#pragma unroll
        for (int j = 0; j < KNBR; j++) {
            float s = w[j];
            s += __shfl_xor_sync(0xffffffffu, s, 4);
            s += __shfl_xor_sync(0xffffffffu, s, 8);
            s += __shfl_xor_sync(0xffffffffu, s, 16);
            ws = (lane == j) ? s : ws;
        }
        if (lane < KNBR)
            w_out[q * KNBR + lane] = ws * 0.125f;  // / NH
    }
}

// ---------------------------------------------------------------------------
extern "C" void kernel_launch(void* const* d_in, const int* in_sizes, int n_in,
                              void* d_out, int out_size)
{
    const float* q_in = (const float*)d_in[0];
    const float* k_in = (const float*)d_in[1];
    const float* v_in = (const float*)d_in[2];
    const int*   idx  = (const int*)  d_in[3];
    const float* Wall = (const float*)d_in[4];
    const float* ball = (const float*)d_in[5];
    const float* Wout = (const float*)d_in[6];
    const float* bout = (const float*)d_in[7];
    float* out = (float*)d_out;

    const int SMEM = 2 * STAGE_WORDS * 4;   // 73728 B
    cudaFuncSetAttribute(qkv_proj_kernel, cudaFuncAttributeMaxDynamicSharedMemorySize, SMEM);
    cudaFuncSetAttribute(outproj_kernel,  cudaFuncAttributeMaxDynamicSharedMemorySize, SMEM);

    // 0) weights -> tf32 bits
    cvt_weights_kernel<<<1024, 256>>>(Wall, Wout);

    // 1) fused q/k/v projections
    dim3 gproj(2, 512, 3);
    qkv_proj_kernel<<<gproj, 256, SMEM>>>(q_in, k_in, v_in, ball);

    // 2) gather attention (warp per query)
    int write_w = (out_size >= QLEN * (EDIM + KNBR)) ? 1 : 0;
    attn_kernel<<<QLEN / 8, 256>>>(idx, out + (size_t)QLEN * EDIM, write_w);

    // 3) output projection -> d_out[0 : Q*E]
    dim3 gout(2, 512, 1);
    outproj_kernel<<<gout, 256, SMEM>>>(bout, out);
}